// round 1
// baseline (speedup 1.0000x reference)
#include <cuda_runtime.h>
#include <math.h>

#define LRW 256
#define LRH 256
#define HRW 1024
#define HRH 1024
#define NC 3
#define RAD 4

#define LRN (NC * LRH * LRW)

// Scratch (no cudaMalloc allowed) — device globals.
__device__ float g_sx[LRN];
__device__ float g_sy[LRN];
__device__ float g_sxy[LRN];
__device__ float g_sxx[LRN];
__device__ float g_A[LRN];
__device__ float g_B[LRN];

// ---------------------------------------------------------------------------
// Low-res pass 1: vertical 9-sums of x, y, x*y, x*x with replicate clamp.
// ---------------------------------------------------------------------------
__global__ void lr_vert(const float* __restrict__ lrx, const float* __restrict__ lry) {
    int idx = blockIdx.x * blockDim.x + threadIdx.x;
    if (idx >= LRN) return;
    int x = idx % LRW;
    int y = (idx / LRW) % LRH;
    int c = idx / (LRW * LRH);
    const float* px = lrx + c * LRH * LRW;
    const float* py = lry + c * LRH * LRW;
    float sx = 0.f, sy = 0.f, sxy = 0.f, sxx = 0.f;
#pragma unroll
    for (int dy = -RAD; dy <= RAD; ++dy) {
        int yy = y + dy;
        yy = yy < 0 ? 0 : (yy > LRH - 1 ? LRH - 1 : yy);
        float vx = px[yy * LRW + x];
        float vy = py[yy * LRW + x];
        sx += vx; sy += vy; sxy += vx * vy; sxx += vx * vx;
    }
    g_sx[idx] = sx; g_sy[idx] = sy; g_sxy[idx] = sxy; g_sxx[idx] = sxx;
}

// ---------------------------------------------------------------------------
// Low-res pass 2: horizontal 9-sums, then A = cov/(var+eps), b = my - A*mx.
// box weight per channel read from box_w input (uniform 1/81).
// ---------------------------------------------------------------------------
__global__ void lr_horz(const float* __restrict__ boxw) {
    int idx = blockIdx.x * blockDim.x + threadIdx.x;
    if (idx >= LRN) return;
    int x = idx % LRW;
    int y = (idx / LRW) % LRH;
    int c = idx / (LRW * LRH);
    int rowbase = c * LRH * LRW + y * LRW;
    float Sx = 0.f, Sy = 0.f, Sxy = 0.f, Sxx = 0.f;
#pragma unroll
    for (int dx = -RAD; dx <= RAD; ++dx) {
        int xx = x + dx;
        xx = xx < 0 ? 0 : (xx > LRW - 1 ? LRW - 1 : xx);
        int j = rowbase + xx;
        Sx += g_sx[j]; Sy += g_sy[j]; Sxy += g_sxy[j]; Sxx += g_sxx[j];
    }
    float w = boxw[c * 81];            // uniform 9x9 weight for this channel
    float mx = Sx * w, my = Sy * w, mxy = Sxy * w, mxx = Sxx * w;
    float A = (mxy - mx * my) / (mxx - mx * mx + 2.0f);  // EPS = 2
    g_A[idx] = A;
    g_B[idx] = my - A * mx;
}

// ---------------------------------------------------------------------------
// High-res fused kernel: bilinear upsample A,b into smem tile (+halo 4),
// separable directional box sums, argmin-|d| selection, trunc+clamp.
// Tile 32x32, block (32,32).
// ---------------------------------------------------------------------------
#define TS 32
#define HALO 4
#define EX (TS + 2 * HALO)  // 40

__global__ void __launch_bounds__(TS * TS) hr_stencil(const float* __restrict__ hrx,
                                                      float* __restrict__ out) {
    __shared__ float As[EX][EX + 1];
    __shared__ float Bs[EX][EX + 1];
    __shared__ float At[TS][EX + 1];
    __shared__ float Ab[TS][EX + 1];
    __shared__ float Bt[TS][EX + 1];
    __shared__ float Bb[TS][EX + 1];

    const int c = blockIdx.z;
    const int tx0 = blockIdx.x * TS;
    const int ty0 = blockIdx.y * TS;
    const int tid = threadIdx.y * TS + threadIdx.x;

    const float* __restrict__ gA = g_A + c * LRH * LRW;
    const float* __restrict__ gB = g_B + c * LRH * LRW;
    const float sc = 255.0f / 1023.0f;   // (src-1)/(out-1), align_corners

    // Stage 1: upsampled A,b for 40x40 extended tile. HR coords clamped to
    // the image -> replicate padding of the upsampled field for free.
    for (int j = tid; j < EX * EX; j += TS * TS) {
        int ly = j / EX, lx = j % EX;
        int Y = ty0 - HALO + ly; Y = Y < 0 ? 0 : (Y > HRH - 1 ? HRH - 1 : Y);
        int X = tx0 - HALO + lx; X = X < 0 ? 0 : (X > HRW - 1 ? HRW - 1 : X);
        float tyf = (float)Y * sc;
        int iy = (int)floorf(tyf); iy = iy > LRH - 2 ? LRH - 2 : iy;
        float fy = tyf - (float)iy;
        float txf = (float)X * sc;
        int ix = (int)floorf(txf); ix = ix > LRW - 2 ? LRW - 2 : ix;
        float fx = txf - (float)ix;
        int b00 = iy * LRW + ix;
        float a0 = gA[b00]       * (1.0f - fy) + gA[b00 + LRW]     * fy;
        float a1 = gA[b00 + 1]   * (1.0f - fy) + gA[b00 + LRW + 1] * fy;
        float b0 = gB[b00]       * (1.0f - fy) + gB[b00 + LRW]     * fy;
        float b1 = gB[b00 + 1]   * (1.0f - fy) + gB[b00 + LRW + 1] * fy;
        As[ly][lx] = a0 * (1.0f - fx) + a1 * fx;
        Bs[ly][lx] = b0 * (1.0f - fx) + b1 * fx;
    }
    __syncthreads();

    // Stage 2: vertical partial sums. For output row ry (smem row ry+4):
    //   top = rows [ry .. ry+4], bot = rows [ry+4 .. ry+8]
    for (int j = tid; j < TS * EX; j += TS * TS) {
        int ry = j / EX, lx = j % EX;
        float at = 0.f, ab = 0.f, bt = 0.f, bb = 0.f;
#pragma unroll
        for (int k = 0; k < 5; ++k) { at += As[ry + k][lx]; bt += Bs[ry + k][lx]; }
#pragma unroll
        for (int k = 4; k < 9; ++k) { ab += As[ry + k][lx]; bb += Bs[ry + k][lx]; }
        At[ry][lx] = at; Ab[ry][lx] = ab; Bt[ry][lx] = bt; Bb[ry][lx] = bb;
    }
    __syncthreads();

    // Stage 3: horizontal 5-sums + direction assembly per output pixel.
    const int tx = threadIdx.x, ty = threadIdx.y;
    float atl = 0.f, atr = 0.f, abl = 0.f, abr = 0.f, acl = 0.f, acr = 0.f;
    float btl = 0.f, btr = 0.f, bbl = 0.f, bbr = 0.f, bcl = 0.f, bcr = 0.f;
#pragma unroll
    for (int k = 0; k < 5; ++k) {
        atl += At[ty][tx + k]; abl += Ab[ty][tx + k]; acl += As[ty + 4][tx + k];
        btl += Bt[ty][tx + k]; bbl += Bb[ty][tx + k]; bcl += Bs[ty + 4][tx + k];
    }
#pragma unroll
    for (int k = 4; k < 9; ++k) {
        atr += At[ty][tx + k]; abr += Ab[ty][tx + k]; acr += As[ty + 4][tx + k];
        btr += Bt[ty][tx + k]; bbr += Bb[ty][tx + k]; bcr += Bs[ty + 4][tx + k];
    }
    float atc = At[ty][tx + 4], abc = Ab[ty][tx + 4];
    float btc = Bt[ty][tx + 4], bbc = Bb[ty][tx + 4];

    const float i45 = 1.0f / 45.0f, i25 = 1.0f / 25.0f;
    float cA[8], cB[8];
    cA[0] = (atl + abl - acl) * i45;  cB[0] = (btl + bbl - bcl) * i45;  // L
    cA[1] = (atr + abr - acr) * i45;  cB[1] = (btr + bbr - bcr) * i45;  // R
    cA[2] = (atl + atr - atc) * i45;  cB[2] = (btl + btr - btc) * i45;  // U
    cA[3] = (abl + abr - abc) * i45;  cB[3] = (bbl + bbr - bbc) * i45;  // D
    cA[4] = atl * i25;                cB[4] = btl * i25;                // NW
    cA[5] = atr * i25;                cB[5] = btr * i25;                // NE
    cA[6] = abl * i25;                cB[6] = bbl * i25;                // SW
    cA[7] = abr * i25;                cB[7] = bbr * i25;                // SE

    const int Y = ty0 + ty, X = tx0 + tx;
    const float im = hrx[(c * HRH + Y) * HRW + X];

    float best = cA[0] * im + cB[0] - im;
    float bestA = fabsf(best);
#pragma unroll
    for (int k = 1; k < 8; ++k) {
        float d = cA[k] * im + cB[k] - im;
        float ad = fabsf(d);
        if (ad < bestA) { bestA = ad; best = d; }   // strict '<' = first-min tie-break
    }
    float r = truncf(best + im);
    r = fminf(fmaxf(r, 0.0f), 255.0f);
    out[(c * HRH + Y) * HRW + X] = r;
}

// ---------------------------------------------------------------------------
extern "C" void kernel_launch(void* const* d_in, const int* in_sizes, int n_in,
                              void* d_out, int out_size) {
    const float* lrx  = (const float*)d_in[0];
    const float* lry  = (const float*)d_in[1];
    const float* hrx  = (const float*)d_in[2];
    const float* boxw = (const float*)d_in[3];
    float* out = (float*)d_out;

    lr_vert<<<(LRN + 255) / 256, 256>>>(lrx, lry);
    lr_horz<<<(LRN + 255) / 256, 256>>>(boxw);

    dim3 grid(HRW / TS, HRH / TS, NC);
    dim3 block(TS, TS);
    hr_stencil<<<grid, block>>>(hrx, out);
}

// round 2
// speedup vs baseline: 1.6753x; 1.6753x over previous
#include <cuda_runtime.h>
#include <math.h>

#define LRW 256
#define LRH 256
#define HRW 1024
#define HRH 1024
#define NC 3
#define RAD 4

#define LRN (NC * LRH * LRW)

// Scratch (no cudaMalloc allowed) — device globals.
__device__ float g_A[LRN];
__device__ float g_B[LRN];

// ---------------------------------------------------------------------------
// Helpers (unrolled, indices resolve to constants -> values stay in registers)
// ---------------------------------------------------------------------------
__device__ __forceinline__ void load12(float* v, const float* base) {
    float4 q0 = *reinterpret_cast<const float4*>(base);
    float4 q1 = *reinterpret_cast<const float4*>(base + 4);
    float4 q2 = *reinterpret_cast<const float4*>(base + 8);
    v[0]=q0.x; v[1]=q0.y; v[2]=q0.z;  v[3]=q0.w;
    v[4]=q1.x; v[5]=q1.y; v[6]=q1.z;  v[7]=q1.w;
    v[8]=q2.x; v[9]=q2.y; v[10]=q2.z; v[11]=q2.w;
}

// h[i] = sum v[i..i+4], i = 0..7  (sliding 5-window)
__device__ __forceinline__ void hsum5(float* h, const float* v) {
    h[0] = v[0] + v[1] + v[2] + v[3] + v[4];
#pragma unroll
    for (int i = 1; i < 8; ++i) h[i] = h[i - 1] - v[i - 1] + v[i + 4];
}

// ---------------------------------------------------------------------------
// Fused low-res kernel: tile 32x32 per block (grid 8x8x3), 256 threads.
// Stage A: load x,y (40x40 with replicate clamp) into smem.
// Stage B: vertical 9-sums of x, y, x*y, x*x.
// Stage C: horizontal 9-sums (vectorized, 4 px/thread), A,b -> global.
// ---------------------------------------------------------------------------
#define LTS 32
#define LEX 40
#define LSP 44   // row stride (floats): mult of 4 for float4, 44 mod 32 spreads banks

__global__ void __launch_bounds__(256) lr_fused(const float* __restrict__ lrx,
                                                const float* __restrict__ lry,
                                                const float* __restrict__ boxw) {
    __shared__ __align__(16) float Xs[LEX * LSP];
    __shared__ __align__(16) float Ys[LEX * LSP];
    __shared__ __align__(16) float Vx[LTS * LSP];
    __shared__ __align__(16) float Vy[LTS * LSP];
    __shared__ __align__(16) float Vxy[LTS * LSP];
    __shared__ __align__(16) float Vxx[LTS * LSP];

    const int c = blockIdx.z;
    const int x0t = blockIdx.x * LTS;
    const int y0t = blockIdx.y * LTS;
    const int tid = threadIdx.x;
    const float* __restrict__ px = lrx + c * LRH * LRW;
    const float* __restrict__ py = lry + c * LRH * LRW;

    // Stage A
    for (int j = tid; j < LEX * LEX; j += 256) {
        int ly = j / LEX, lx = j % LEX;
        int Y = y0t - RAD + ly; Y = Y < 0 ? 0 : (Y > LRH - 1 ? LRH - 1 : Y);
        int X = x0t - RAD + lx; X = X < 0 ? 0 : (X > LRW - 1 ? LRW - 1 : X);
        Xs[ly * LSP + lx] = px[Y * LRW + X];
        Ys[ly * LSP + lx] = py[Y * LRW + X];
    }
    __syncthreads();

    // Stage B: vertical 9-sums
    for (int j = tid; j < LTS * LEX; j += 256) {
        int ry = j / LEX, lx = j % LEX;
        float sx = 0.f, sy = 0.f, sxy = 0.f, sxx = 0.f;
#pragma unroll
        for (int k = 0; k < 9; ++k) {
            float vx = Xs[(ry + k) * LSP + lx];
            float vy = Ys[(ry + k) * LSP + lx];
            sx += vx; sy += vy; sxy += vx * vy; sxx += vx * vx;
        }
        Vx[ry * LSP + lx] = sx;  Vy[ry * LSP + lx] = sy;
        Vxy[ry * LSP + lx] = sxy; Vxx[ry * LSP + lx] = sxx;
    }
    __syncthreads();

    // Stage C: horizontal 9-sums, 4 consecutive px per thread
    const int ty = tid >> 3;
    const int x0 = (tid & 7) << 2;
    float vx[12], vy[12], vxy[12], vxx[12];
    load12(vx,  &Vx[ty * LSP + x0]);
    load12(vy,  &Vy[ty * LSP + x0]);
    load12(vxy, &Vxy[ty * LSP + x0]);
    load12(vxx, &Vxx[ty * LSP + x0]);

    float hx[4], hy[4], hxy[4], hxx[4];
    hx[0] = vx[0]+vx[1]+vx[2]+vx[3]+vx[4]+vx[5]+vx[6]+vx[7]+vx[8];
    hy[0] = vy[0]+vy[1]+vy[2]+vy[3]+vy[4]+vy[5]+vy[6]+vy[7]+vy[8];
    hxy[0]= vxy[0]+vxy[1]+vxy[2]+vxy[3]+vxy[4]+vxy[5]+vxy[6]+vxy[7]+vxy[8];
    hxx[0]= vxx[0]+vxx[1]+vxx[2]+vxx[3]+vxx[4]+vxx[5]+vxx[6]+vxx[7]+vxx[8];
#pragma unroll
    for (int i = 1; i < 4; ++i) {
        hx[i]  = hx[i-1]  - vx[i-1]  + vx[i+8];
        hy[i]  = hy[i-1]  - vy[i-1]  + vy[i+8];
        hxy[i] = hxy[i-1] - vxy[i-1] + vxy[i+8];
        hxx[i] = hxx[i-1] - vxx[i-1] + vxx[i+8];
    }

    const float w = boxw[c * 81];
    float4 Ao, Bo;
    float A_[4], B_[4];
#pragma unroll
    for (int p = 0; p < 4; ++p) {
        float mx = hx[p] * w, my = hy[p] * w, mxy = hxy[p] * w, mxx = hxx[p] * w;
        float A = (mxy - mx * my) / (mxx - mx * mx + 2.0f);   // EPS = 2
        A_[p] = A; B_[p] = my - A * mx;
    }
    Ao = make_float4(A_[0], A_[1], A_[2], A_[3]);
    Bo = make_float4(B_[0], B_[1], B_[2], B_[3]);
    int o = c * LRH * LRW + (y0t + ty) * LRW + (x0t + x0);
    *reinterpret_cast<float4*>(&g_A[o]) = Ao;
    *reinterpret_cast<float4*>(&g_B[o]) = Bo;
}

// ---------------------------------------------------------------------------
// High-res fused kernel: tile 32x32 per block (grid 32x32x3), 256 threads.
// Stage 1: bilinear upsample A,b into 40x40 smem tile (halo 4; HR-coord clamp
//          = replicate pad for free).
// Stage 2: single sliding vertical 5-sum array T per field:
//          T[ry] = sum rows[ry..ry+4]; top(ry)=T[ry], bot(ry)=T[ry+4].
// Stage 3: 4 px/thread, float4 smem loads, sliding horizontal 5-sums,
//          8-direction assembly, strict-< argmin, trunc+clamp.
// ---------------------------------------------------------------------------
#define TS 32
#define HALO 4
#define EX 40
#define SP 44
#define TROWS 36

__global__ void __launch_bounds__(256, 3) hr_stencil(const float* __restrict__ hrx,
                                                     float* __restrict__ out) {
    __shared__ __align__(16) float As[EX * SP];
    __shared__ __align__(16) float Bs[EX * SP];
    __shared__ __align__(16) float TA[TROWS * SP];
    __shared__ __align__(16) float TB[TROWS * SP];

    const int c = blockIdx.z;
    const int tx0 = blockIdx.x * TS;
    const int ty0 = blockIdx.y * TS;
    const int tid = threadIdx.x;

    const float* __restrict__ gA = g_A + c * LRH * LRW;
    const float* __restrict__ gB = g_B + c * LRH * LRW;
    const float sc = 255.0f / 1023.0f;   // (src-1)/(out-1), align_corners

    // Stage 1: bilinear upsample into extended tile
    for (int j = tid; j < EX * EX; j += 256) {
        int ly = j / EX, lx = j % EX;
        int Y = ty0 - HALO + ly; Y = Y < 0 ? 0 : (Y > HRH - 1 ? HRH - 1 : Y);
        int X = tx0 - HALO + lx; X = X < 0 ? 0 : (X > HRW - 1 ? HRW - 1 : X);
        float tyf = (float)Y * sc;
        int iy = (int)floorf(tyf); iy = iy > LRH - 2 ? LRH - 2 : iy;
        float fy = tyf - (float)iy;
        float txf = (float)X * sc;
        int ix = (int)floorf(txf); ix = ix > LRW - 2 ? LRW - 2 : ix;
        float fx = txf - (float)ix;
        int b00 = iy * LRW + ix;
        float a0 = gA[b00]       * (1.0f - fy) + gA[b00 + LRW]     * fy;
        float a1 = gA[b00 + 1]   * (1.0f - fy) + gA[b00 + LRW + 1] * fy;
        float b0 = gB[b00]       * (1.0f - fy) + gB[b00 + LRW]     * fy;
        float b1 = gB[b00 + 1]   * (1.0f - fy) + gB[b00 + LRW + 1] * fy;
        As[ly * SP + lx] = a0 * (1.0f - fx) + a1 * fx;
        Bs[ly * SP + lx] = b0 * (1.0f - fx) + b1 * fx;
    }
    __syncthreads();

    // Stage 2: T[ry] = sum rows[ry..ry+4], ry in [0,36), sliding per column.
    if (tid < 160) {
        int field = tid / 80;          // 0 = A, 1 = B
        int r2 = tid % 80;
        int col = r2 % 40;
        int ry0 = (r2 / 40) * 18;      // halves: rows [0,18) and [18,36)
        const float* __restrict__ S = field ? Bs : As;
        float* __restrict__ T = field ? TB : TA;
        float s = S[(ry0 + 0) * SP + col] + S[(ry0 + 1) * SP + col] +
                  S[(ry0 + 2) * SP + col] + S[(ry0 + 3) * SP + col] +
                  S[(ry0 + 4) * SP + col];
        T[ry0 * SP + col] = s;
#pragma unroll
        for (int r = 1; r < 18; ++r) {
            s += S[(ry0 + r + 4) * SP + col] - S[(ry0 + r - 1) * SP + col];
            T[(ry0 + r) * SP + col] = s;
        }
    }
    __syncthreads();

    // Stage 3: 4 consecutive output px per thread
    const int ty = tid >> 3;            // output row 0..31
    const int x0 = (tid & 7) << 2;      // output col base 0..28

    float vAt[12], vAb[12], vAc[12], vBt[12], vBb[12], vBc[12];
    load12(vAt, &TA[ty * SP + x0]);
    load12(vAb, &TA[(ty + 4) * SP + x0]);
    load12(vAc, &As[(ty + 4) * SP + x0]);
    load12(vBt, &TB[ty * SP + x0]);
    load12(vBb, &TB[(ty + 4) * SP + x0]);
    load12(vBc, &Bs[(ty + 4) * SP + x0]);

    float hAt[8], hAb[8], hAc[8], hBt[8], hBb[8], hBc[8];
    hsum5(hAt, vAt); hsum5(hAb, vAb); hsum5(hAc, vAc);
    hsum5(hBt, vBt); hsum5(hBb, vBb); hsum5(hBc, vBc);

    const int Y = ty0 + ty;
    const float4 im4 = *reinterpret_cast<const float4*>(
        &hrx[(c * HRH + Y) * HRW + tx0 + x0]);
    const float imv[4] = {im4.x, im4.y, im4.z, im4.w};

    const float i45 = 1.0f / 45.0f, i25 = 1.0f / 25.0f;
    float res[4];
#pragma unroll
    for (int p = 0; p < 4; ++p) {
        float atl = hAt[p], atr = hAt[p + 4];
        float abl = hAb[p], abr = hAb[p + 4];
        float acl = hAc[p], acr = hAc[p + 4];
        float btl = hBt[p], btr = hBt[p + 4];
        float bbl = hBb[p], bbr = hBb[p + 4];
        float bcl = hBc[p], bcr = hBc[p + 4];
        float atc = vAt[p + 4], abc = vAb[p + 4];
        float btc = vBt[p + 4], bbc = vBb[p + 4];

        float cA[8], cB[8];
        cA[0] = (atl + abl - acl) * i45;  cB[0] = (btl + bbl - bcl) * i45;  // L
        cA[1] = (atr + abr - acr) * i45;  cB[1] = (btr + bbr - bcr) * i45;  // R
        cA[2] = (atl + atr - atc) * i45;  cB[2] = (btl + btr - btc) * i45;  // U
        cA[3] = (abl + abr - abc) * i45;  cB[3] = (bbl + bbr - bbc) * i45;  // D
        cA[4] = atl * i25;                cB[4] = btl * i25;                // NW
        cA[5] = atr * i25;                cB[5] = btr * i25;                // NE
        cA[6] = abl * i25;                cB[6] = bbl * i25;                // SW
        cA[7] = abr * i25;                cB[7] = bbr * i25;                // SE

        const float im = imv[p];
        float best = cA[0] * im + cB[0] - im;
        float bestA = fabsf(best);
#pragma unroll
        for (int k = 1; k < 8; ++k) {
            float d = cA[k] * im + cB[k] - im;
            float ad = fabsf(d);
            if (ad < bestA) { bestA = ad; best = d; }  // strict '<' = first-min
        }
        float r = truncf(best + im);
        res[p] = fminf(fmaxf(r, 0.0f), 255.0f);
    }
    *reinterpret_cast<float4*>(&out[(c * HRH + Y) * HRW + tx0 + x0]) =
        make_float4(res[0], res[1], res[2], res[3]);
}

// ---------------------------------------------------------------------------
extern "C" void kernel_launch(void* const* d_in, const int* in_sizes, int n_in,
                              void* d_out, int out_size) {
    const float* lrx  = (const float*)d_in[0];
    const float* lry  = (const float*)d_in[1];
    const float* hrx  = (const float*)d_in[2];
    const float* boxw = (const float*)d_in[3];
    float* out = (float*)d_out;

    dim3 lgrid(LRW / LTS, LRH / LTS, NC);
    lr_fused<<<lgrid, 256>>>(lrx, lry, boxw);

    dim3 grid(HRW / TS, HRH / TS, NC);
    hr_stencil<<<grid, 256>>>(hrx, out);
}